// round 2
// baseline (speedup 1.0000x reference)
#include <cuda_runtime.h>
#include <cuda_bf16.h>
#include <cstdint>

#define N_NODES 50000
#define N_EDGES 800000
#define F 128           // feature width all layers
#define SCAN_BLK 1024
#define NSCAN ((N_NODES + SCAN_BLK - 1) / SCAN_BLK)   // 49

// ---------------- scratch (static device memory; no allocations) -------------
__device__ float g_h[2][(size_t)N_NODES * F];   // ping-pong hidden states
__device__ float g_mean[(size_t)N_NODES * F];   // aggregated mean per node
__device__ int   g_deg[N_NODES];
__device__ int   g_scan[N_NODES];
__device__ int   g_off[N_NODES];
__device__ int   g_cursor[N_NODES];
__device__ int   g_bsum[64];
__device__ int   g_bsumx[64];
__device__ int   g_srcs[N_EDGES];

// ---------------- CSR build --------------------------------------------------
__global__ void k_zero_deg() {
    int i = blockIdx.x * blockDim.x + threadIdx.x;
    if (i < N_NODES) g_deg[i] = 0;
}

// edge_index is int32 (JAX x64 disabled -> int64 request silently becomes int32)
__global__ void k_hist(const int* __restrict__ edge) {
    int e = blockIdx.x * blockDim.x + threadIdx.x;
    if (e < N_EDGES) {
        unsigned dst = (unsigned)edge[N_EDGES + e];
        if (dst < N_NODES) atomicAdd(&g_deg[dst], 1);
    }
}

__global__ void k_scan1() {
    __shared__ int s[SCAN_BLK];
    int tid = threadIdx.x;
    int i = blockIdx.x * SCAN_BLK + tid;
    int v = (i < N_NODES) ? g_deg[i] : 0;
    s[tid] = v;
    __syncthreads();
    for (int o = 1; o < SCAN_BLK; o <<= 1) {
        int t = (tid >= o) ? s[tid - o] : 0;
        __syncthreads();
        s[tid] += t;
        __syncthreads();
    }
    if (i < N_NODES) g_scan[i] = s[tid];
    if (tid == SCAN_BLK - 1) g_bsum[blockIdx.x] = s[tid];
}

__global__ void k_scan2() {
    __shared__ int s[64];
    int tid = threadIdx.x;
    int v = (tid < NSCAN) ? g_bsum[tid] : 0;
    s[tid] = v;
    __syncthreads();
    for (int o = 1; o < 64; o <<= 1) {
        int t = (tid >= o) ? s[tid - o] : 0;
        __syncthreads();
        s[tid] += t;
        __syncthreads();
    }
    if (tid < NSCAN) g_bsumx[tid] = s[tid] - v;  // exclusive
}

__global__ void k_scan3() {
    int i = blockIdx.x * blockDim.x + threadIdx.x;
    if (i < N_NODES) {
        int off = g_scan[i] - g_deg[i] + g_bsumx[i / SCAN_BLK];
        g_off[i] = off;
        g_cursor[i] = off;
    }
}

__global__ void k_scatter(const int* __restrict__ edge) {
    int e = blockIdx.x * blockDim.x + threadIdx.x;
    if (e < N_EDGES) {
        unsigned src = (unsigned)edge[e];
        unsigned dst = (unsigned)edge[N_EDGES + e];
        if (dst < N_NODES && src < N_NODES) {
            int pos = atomicAdd(&g_cursor[dst], 1);
            g_srcs[pos] = (int)src;
        }
    }
}

// ---------------- aggregation: one warp per node ----------------------------
__global__ void k_agg(const float* __restrict__ xin) {
    int warp = (blockIdx.x * blockDim.x + threadIdx.x) >> 5;
    if (warp >= N_NODES) return;
    int lane = threadIdx.x & 31;
    int d = g_deg[warp];
    int o = g_off[warp];
    float4 acc = make_float4(0.f, 0.f, 0.f, 0.f);
    for (int e = 0; e < d; e++) {
        int s = g_srcs[o + e];  // lane-uniform (broadcast)
        float4 v = ((const float4*)(xin + (size_t)s * F))[lane];
        acc.x += v.x; acc.y += v.y; acc.z += v.z; acc.w += v.w;
    }
    float inv = (d > 0) ? 1.0f / (float)d : 0.0f;
    acc.x *= inv; acc.y *= inv; acc.z *= inv; acc.w *= inv;
    ((float4*)(g_mean + (size_t)warp * F))[lane] = acc;
}

// ---------------- fused SGEMM: relu(mean@Wl^T + h@Wr^T + bl) -----------------
// BM=128 nodes, BN=128 outputs, K=256 (128 from mean*Wl, 128 from h*Wr), BK=16
__global__ void __launch_bounds__(256, 2) k_gemm(
    const float* __restrict__ Ah,   // current hidden [N,128]
    const float* __restrict__ Wl, const float* __restrict__ Wr,
    const float* __restrict__ bl,
    float* __restrict__ Cout)
{
    __shared__ __align__(16) float As[16][128];
    __shared__ __align__(16) float Bs[16][128];

    int tid = threadIdx.x;
    int tx = tid & 15;       // output-col group
    int ty = tid >> 4;       // node-row group
    int m0 = blockIdx.x * 128;

    float acc[8][8];
#pragma unroll
    for (int r = 0; r < 8; r++)
#pragma unroll
        for (int c = 0; c < 8; c++) acc[r][c] = 0.f;

    for (int kt = 0; kt < 16; kt++) {
        const float* A = (kt < 8) ? g_mean : Ah;
        const float* W = (kt < 8) ? Wl : Wr;
        int k0 = (kt & 7) * 16;

        // load A tile (128 rows x 16 cols), transpose into As[k][row]
#pragma unroll
        for (int q = 0; q < 2; q++) {
            int f = tid * 2 + q;        // 0..511
            int col4 = f & 3;
            int row = f >> 2;
            float4 v = make_float4(0.f, 0.f, 0.f, 0.f);
            if (m0 + row < N_NODES)
                v = *(const float4*)(A + (size_t)(m0 + row) * F + k0 + col4 * 4);
            As[col4 * 4 + 0][row] = v.x;
            As[col4 * 4 + 1][row] = v.y;
            As[col4 * 4 + 2][row] = v.z;
            As[col4 * 4 + 3][row] = v.w;
        }
        // load W tile: Bs[k][j] = W[j][k0+k]
#pragma unroll
        for (int q = 0; q < 2; q++) {
            int f = tid * 2 + q;
            int col4 = f & 3;
            int j = f >> 2;
            float4 v = *(const float4*)(W + (size_t)j * F + k0 + col4 * 4);
            Bs[col4 * 4 + 0][j] = v.x;
            Bs[col4 * 4 + 1][j] = v.y;
            Bs[col4 * 4 + 2][j] = v.z;
            Bs[col4 * 4 + 3][j] = v.w;
        }
        __syncthreads();

#pragma unroll
        for (int kk = 0; kk < 16; kk++) {
            float4 a0 = *(const float4*)&As[kk][ty * 8];
            float4 a1 = *(const float4*)&As[kk][ty * 8 + 4];
            float4 b0 = *(const float4*)&Bs[kk][tx * 8];
            float4 b1 = *(const float4*)&Bs[kk][tx * 8 + 4];
            float a[8] = {a0.x, a0.y, a0.z, a0.w, a1.x, a1.y, a1.z, a1.w};
            float b[8] = {b0.x, b0.y, b0.z, b0.w, b1.x, b1.y, b1.z, b1.w};
#pragma unroll
            for (int r = 0; r < 8; r++)
#pragma unroll
                for (int c = 0; c < 8; c++)
                    acc[r][c] += a[r] * b[c];
        }
        __syncthreads();
    }

    // epilogue: bias + relu
    float bias[8];
#pragma unroll
    for (int c = 0; c < 8; c++) bias[c] = bl[tx * 8 + c];

#pragma unroll
    for (int r = 0; r < 8; r++) {
        int row = m0 + ty * 8 + r;
        if (row < N_NODES) {
            float v[8];
#pragma unroll
            for (int c = 0; c < 8; c++) {
                float t = acc[r][c] + bias[c];
                v[c] = t > 0.f ? t : 0.f;
            }
            *(float4*)(Cout + (size_t)row * F + tx * 8) = make_float4(v[0], v[1], v[2], v[3]);
            *(float4*)(Cout + (size_t)row * F + tx * 8 + 4) = make_float4(v[4], v[5], v[6], v[7]);
        }
    }
}

// ---------------- final linear: out[i] = h[i] . Wf + bf ---------------------
__global__ void k_final(const float* __restrict__ h,
                        const float* __restrict__ Wf,
                        const float* __restrict__ bf,
                        float* __restrict__ out)
{
    int warp = (blockIdx.x * blockDim.x + threadIdx.x) >> 5;
    if (warp >= N_NODES) return;
    int lane = threadIdx.x & 31;
    float4 hv = ((const float4*)(h + (size_t)warp * F))[lane];
    float4 wv = ((const float4*)Wf)[lane];
    float s = hv.x * wv.x + hv.y * wv.y + hv.z * wv.z + hv.w * wv.w;
#pragma unroll
    for (int o = 16; o > 0; o >>= 1) s += __shfl_down_sync(0xFFFFFFFFu, s, o);
    if (lane == 0) out[warp] = s + bf[0];
}

// ---------------- launch -----------------------------------------------------
extern "C" void kernel_launch(void* const* d_in, const int* in_sizes, int n_in,
                              void* d_out, int out_size)
{
    const float* x    = (const float*)d_in[0];
    const int*   edge = (const int*)d_in[1];   // int32! (JAX x64 disabled)
    const float* Wl[3] = {(const float*)d_in[2], (const float*)d_in[5], (const float*)d_in[8]};
    const float* bl[3] = {(const float*)d_in[3], (const float*)d_in[6], (const float*)d_in[9]};
    const float* Wr[3] = {(const float*)d_in[4], (const float*)d_in[7], (const float*)d_in[10]};
    const float* Wf = (const float*)d_in[11];
    const float* bf = (const float*)d_in[12];
    float* out = (float*)d_out;

    void* p = nullptr;
    cudaGetSymbolAddress(&p, g_h);
    float* h0 = (float*)p;
    float* h1 = h0 + (size_t)N_NODES * F;

    // CSR build (by dst)
    k_zero_deg<<<(N_NODES + 255) / 256, 256>>>();
    k_hist<<<(N_EDGES + 255) / 256, 256>>>(edge);
    k_scan1<<<NSCAN, SCAN_BLK>>>();
    k_scan2<<<1, 64>>>();
    k_scan3<<<(N_NODES + 255) / 256, 256>>>();
    k_scatter<<<(N_EDGES + 255) / 256, 256>>>(edge);

    const int AGG_BLOCKS = (N_NODES * 32 + 255) / 256;
    const int GEMM_BLOCKS = (N_NODES + 127) / 128;

    // layer 0: x -> h0
    k_agg<<<AGG_BLOCKS, 256>>>(x);
    k_gemm<<<GEMM_BLOCKS, 256>>>(x, Wl[0], Wr[0], bl[0], h0);
    // layer 1: h0 -> h1
    k_agg<<<AGG_BLOCKS, 256>>>(h0);
    k_gemm<<<GEMM_BLOCKS, 256>>>(h0, Wl[1], Wr[1], bl[1], h1);
    // layer 2: h1 -> h0
    k_agg<<<AGG_BLOCKS, 256>>>(h1);
    k_gemm<<<GEMM_BLOCKS, 256>>>(h1, Wl[2], Wr[2], bl[2], h0);
    // final linear
    k_final<<<AGG_BLOCKS, 256>>>(h0, Wf, bf, out);
}

// round 4
// speedup vs baseline: 1.7080x; 1.7080x over previous
#include <cuda_runtime.h>
#include <cuda_bf16.h>
#include <cstdint>

#define N_NODES 50000
#define N_EDGES 800000
#define F 128
#define SCAN_BLK 1024
#define NSCAN ((N_NODES + SCAN_BLK - 1) / SCAN_BLK)   // 49

// ---------------- scratch (static device memory) -----------------------------
__device__ unsigned g_xp[(size_t)N_NODES * F];          // packed split-bf16 x (hi lo)
__device__ unsigned g_hp[2][(size_t)N_NODES * F];       // packed hidden (ping-pong)
__device__ unsigned g_meanp[(size_t)N_NODES * F];       // packed mean
__device__ __nv_bfloat16 g_whi[3 * 128 * 256];          // combined [Wl|Wr] hi
__device__ __nv_bfloat16 g_wlo[3 * 128 * 256];          // combined [Wl|Wr] lo
__device__ int g_deg[N_NODES];
__device__ int g_scan[N_NODES];
__device__ int g_off[N_NODES];
__device__ int g_cursor[N_NODES];
__device__ int g_bsum[64];
__device__ int g_bsumx[64];
__device__ int g_srcs[N_EDGES];

// ---------------- pack/unpack helpers ----------------------------------------
__device__ __forceinline__ float unpack_v(unsigned u) {
    return __uint_as_float(u << 16) + __uint_as_float(u & 0xFFFF0000u);
}
__device__ __forceinline__ unsigned pack_v(float v) {
    __nv_bfloat16 h = __float2bfloat16(v);
    unsigned hb = (unsigned)__bfloat16_as_ushort(h);
    float hf = __uint_as_float(hb << 16);
    __nv_bfloat16 l = __float2bfloat16(v - hf);
    unsigned lb = (unsigned)__bfloat16_as_ushort(l);
    return hb | (lb << 16);
}

// ---------------- warp-mma helpers --------------------------------------------
__device__ __forceinline__ unsigned smem_u32(const void* p) {
    unsigned a;
    asm("{ .reg .u64 t; cvta.to.shared.u64 t, %1; cvt.u32.u64 %0, t; }" : "=r"(a) : "l"(p));
    return a;
}
__device__ __forceinline__ void ldsm_x4(unsigned* r, unsigned addr) {
    asm volatile("ldmatrix.sync.aligned.m8n8.x4.shared.b16 {%0,%1,%2,%3}, [%4];"
                 : "=r"(r[0]), "=r"(r[1]), "=r"(r[2]), "=r"(r[3]) : "r"(addr));
}
__device__ __forceinline__ void mma16816(float* c, const unsigned* a, const unsigned* b) {
    asm volatile(
        "mma.sync.aligned.m16n8k16.row.col.f32.bf16.bf16.f32 "
        "{%0,%1,%2,%3}, {%4,%5,%6,%7}, {%8,%9}, {%0,%1,%2,%3};"
        : "+f"(c[0]), "+f"(c[1]), "+f"(c[2]), "+f"(c[3])
        : "r"(a[0]), "r"(a[1]), "r"(a[2]), "r"(a[3]), "r"(b[0]), "r"(b[1]));
}

// ---------------- CSR build ---------------------------------------------------
__global__ void k_zero_deg() {
    int i = blockIdx.x * blockDim.x + threadIdx.x;
    if (i < N_NODES) g_deg[i] = 0;
}
__global__ void k_hist(const int* __restrict__ edge) {
    int e = blockIdx.x * blockDim.x + threadIdx.x;
    if (e < N_EDGES) {
        unsigned dst = (unsigned)edge[N_EDGES + e];
        if (dst < N_NODES) atomicAdd(&g_deg[dst], 1);
    }
}
__global__ void k_scan1() {
    __shared__ int s[SCAN_BLK];
    int tid = threadIdx.x;
    int i = blockIdx.x * SCAN_BLK + tid;
    int v = (i < N_NODES) ? g_deg[i] : 0;
    s[tid] = v;
    __syncthreads();
    for (int o = 1; o < SCAN_BLK; o <<= 1) {
        int t = (tid >= o) ? s[tid - o] : 0;
        __syncthreads();
        s[tid] += t;
        __syncthreads();
    }
    if (i < N_NODES) g_scan[i] = s[tid];
    if (tid == SCAN_BLK - 1) g_bsum[blockIdx.x] = s[tid];
}
__global__ void k_scan2() {
    __shared__ int s[64];
    int tid = threadIdx.x;
    int v = (tid < NSCAN) ? g_bsum[tid] : 0;
    s[tid] = v;
    __syncthreads();
    for (int o = 1; o < 64; o <<= 1) {
        int t = (tid >= o) ? s[tid - o] : 0;
        __syncthreads();
        s[tid] += t;
        __syncthreads();
    }
    if (tid < NSCAN) g_bsumx[tid] = s[tid] - v;
}
__global__ void k_scan3() {
    int i = blockIdx.x * blockDim.x + threadIdx.x;
    if (i < N_NODES) {
        int off = g_scan[i] - g_deg[i] + g_bsumx[i / SCAN_BLK];
        g_off[i] = off;
        g_cursor[i] = off;
    }
}
__global__ void k_scatter(const int* __restrict__ edge) {
    int e = blockIdx.x * blockDim.x + threadIdx.x;
    if (e < N_EDGES) {
        unsigned src = (unsigned)edge[e];
        unsigned dst = (unsigned)edge[N_EDGES + e];
        if (dst < N_NODES && src < N_NODES) {
            int pos = atomicAdd(&g_cursor[dst], 1);
            g_srcs[pos] = (int)src;
        }
    }
}

// ---------------- packing -------------------------------------------------------
__global__ void k_pack_x(const float* __restrict__ x) {
    int i = blockIdx.x * blockDim.x + threadIdx.x;
    if (i < N_NODES * F / 4) {
        float4 v = ((const float4*)x)[i];
        uint4 o;
        o.x = pack_v(v.x); o.y = pack_v(v.y); o.z = pack_v(v.z); o.w = pack_v(v.w);
        ((uint4*)g_xp)[i] = o;
    }
}
__global__ void k_pack_w(const float* Wl0, const float* Wr0,
                         const float* Wl1, const float* Wr1,
                         const float* Wl2, const float* Wr2) {
    int idx = blockIdx.x * blockDim.x + threadIdx.x;
    if (idx >= 3 * 128 * 256) return;
    int L = idx / (128 * 256);
    int r = idx % (128 * 256);
    int n = r / 256;
    int k = r % 256;
    const float* Wl = (L == 0) ? Wl0 : (L == 1) ? Wl1 : Wl2;
    const float* Wr = (L == 0) ? Wr0 : (L == 1) ? Wr1 : Wr2;
    float v = (k < 128) ? Wl[n * 128 + k] : Wr[n * 128 + (k - 128)];
    unsigned p = pack_v(v);
    __nv_bfloat16_raw hr; hr.x = (unsigned short)(p & 0xFFFF);
    __nv_bfloat16_raw lr; lr.x = (unsigned short)(p >> 16);
    g_whi[idx] = __nv_bfloat16(hr);
    g_wlo[idx] = __nv_bfloat16(lr);
}

// ---------------- aggregation: one warp per node (packed) ----------------------
__global__ void k_agg(const unsigned* __restrict__ in) {
    int warp = (blockIdx.x * blockDim.x + threadIdx.x) >> 5;
    if (warp >= N_NODES) return;
    int lane = threadIdx.x & 31;
    int d = g_deg[warp];
    int o = g_off[warp];
    float a0 = 0.f, a1 = 0.f, a2 = 0.f, a3 = 0.f;
    for (int e = 0; e < d; e++) {
        int s = g_srcs[o + e];
        uint4 p = ((const uint4*)(in + (size_t)s * F))[lane];
        a0 += unpack_v(p.x); a1 += unpack_v(p.y);
        a2 += unpack_v(p.z); a3 += unpack_v(p.w);
    }
    float inv = (d > 0) ? 1.0f / (float)d : 0.0f;
    uint4 outp;
    outp.x = pack_v(a0 * inv); outp.y = pack_v(a1 * inv);
    outp.z = pack_v(a2 * inv); outp.w = pack_v(a3 * inv);
    ((uint4*)(g_meanp + (size_t)warp * F))[lane] = outp;
}

// ---------------- HMMA GEMM: relu([mean|h] @ [Wl|Wr]^T + b), split bf16 --------
// CTA: 128 rows x 128 cols, K=256 in 4 chunks of 64. 8 warps: 2 (M) x 4 (N),
// warp tile 64x32. 3-term split: Ahi*Whi + Ahi*Wlo + Alo*Whi.
#define SM_BIAS 0
#define SM_AHI  512
#define SM_ALO  (SM_AHI + 16384)
#define SM_WHI  (SM_ALO + 16384)
#define SM_WLO  (SM_WHI + 16384)
#define SM_TOTAL (SM_WLO + 16384)     // 66048 bytes

// swizzled row-major: row stride 128B (64 bf16), 16B chunks XOR'd by row&7
__device__ __forceinline__ unsigned swoff(int row, int k) {
    return (unsigned)(row * 128 + ((((k >> 3) ^ row) & 7) << 4) + (k & 7) * 2);
}

__global__ void __launch_bounds__(256, 1) k_gemm(
    const unsigned* __restrict__ Am,
    const unsigned* __restrict__ Ah,
    const __nv_bfloat16* __restrict__ Whi,
    const __nv_bfloat16* __restrict__ Wlo,
    const float* __restrict__ bl,
    unsigned* __restrict__ outp)
{
    extern __shared__ __align__(16) char smem[];
    unsigned sb = smem_u32(smem);
    int tid = threadIdx.x;
    int wid = tid >> 5;
    int lane = tid & 31;
    int wm = wid & 1;        // M half (64 rows)
    int wn = wid >> 1;       // N quarter (32 cols)
    int m0 = blockIdx.x * 128;

    if (tid < 128) *(float*)(smem + SM_BIAS + tid * 4) = bl[tid];

    float acc[4][4][4];
#pragma unroll
    for (int a = 0; a < 4; a++)
#pragma unroll
        for (int b = 0; b < 4; b++)
#pragma unroll
            for (int c = 0; c < 4; c++) acc[a][b][c] = 0.f;

    for (int chunk = 0; chunk < 4; chunk++) {
        const unsigned* ap = (chunk < 2) ? Am : Ah;
        int kcA = (chunk & 1) * 64;
        int kcW = chunk * 64;
        __syncthreads();
        // A chunk: 128 rows x 64 cols packed -> hi/lo planes
        for (int i = tid; i < 2048; i += 256) {
            int row = i >> 4;
            int k4 = (i & 15) * 4;
            uint4 p = make_uint4(0, 0, 0, 0);
            if (m0 + row < N_NODES)
                p = *(const uint4*)(ap + (size_t)(m0 + row) * F + kcA + k4);
            uint2 h, l;
            h.x = (p.x & 0xFFFFu) | (p.y << 16);
            h.y = (p.z & 0xFFFFu) | (p.w << 16);
            l.x = (p.x >> 16) | (p.y & 0xFFFF0000u);
            l.y = (p.z >> 16) | (p.w & 0xFFFF0000u);
            unsigned off = swoff(row, k4);
            *(uint2*)(smem + SM_AHI + off) = h;
            *(uint2*)(smem + SM_ALO + off) = l;
        }
        // W chunk: 128 n-rows x 64 k-cols, hi + lo
        for (int i = tid; i < 1024; i += 256) {
            int n = i >> 3;
            int k8 = (i & 7) * 8;
            unsigned off = swoff(n, k8);
            *(uint4*)(smem + SM_WHI + off) = *(const uint4*)(Whi + n * 256 + kcW + k8);
            *(uint4*)(smem + SM_WLO + off) = *(const uint4*)(Wlo + n * 256 + kcW + k8);
        }
        __syncthreads();

#pragma unroll
        for (int ks = 0; ks < 4; ks++) {
            int kl = ks * 16;
            // A fragments (4 m-frags, hi & lo)
            unsigned ahi[16], alo[16];
            int mrl = ((lane >> 3) & 1) * 8 + (lane & 7);
            int kkA = kl + (lane >> 4) * 8;
#pragma unroll
            for (int mf = 0; mf < 4; mf++) {
                int mrow = wm * 64 + mf * 16 + mrl;
                unsigned offA = (unsigned)(mrow * 128 + ((((kkA >> 3) ^ mrow) & 7) << 4));
                ldsm_x4(&ahi[mf * 4], sb + SM_AHI + offA);
                ldsm_x4(&alo[mf * 4], sb + SM_ALO + offA);
            }
            // B fragments (2 pairs of n-frags, hi & lo)
            unsigned bhi[8], blo[8];
            int nrl = (lane >> 4) * 8 + (lane & 7);
            int kkB = kl + ((lane >> 3) & 1) * 8;
#pragma unroll
            for (int nf2 = 0; nf2 < 2; nf2++) {
                int nrow = wn * 32 + nf2 * 16 + nrl;
                unsigned offB = (unsigned)(nrow * 128 + ((((kkB >> 3) ^ nrow) & 7) << 4));
                ldsm_x4(&bhi[nf2 * 4], sb + SM_WHI + offB);
                ldsm_x4(&blo[nf2 * 4], sb + SM_WLO + offB);
            }
#pragma unroll
            for (int mf = 0; mf < 4; mf++)
#pragma unroll
                for (int nf = 0; nf < 4; nf++) {
                    const unsigned* bh = &bhi[(nf >> 1) * 4 + (nf & 1) * 2];
                    const unsigned* blp = &blo[(nf >> 1) * 4 + (nf & 1) * 2];
                    mma16816(acc[mf][nf], &ahi[mf * 4], bh);
                    mma16816(acc[mf][nf], &ahi[mf * 4], blp);
                    mma16816(acc[mf][nf], &alo[mf * 4], bh);
                }
        }
    }

    // epilogue: bias + relu + pack
    const float* bias = (const float*)(smem + SM_BIAS);
#pragma unroll
    for (int mf = 0; mf < 4; mf++) {
        int ra = m0 + wm * 64 + mf * 16 + (lane >> 2);
        int rb = ra + 8;
#pragma unroll
        for (int nf = 0; nf < 4; nf++) {
            int col = wn * 32 + nf * 8 + (lane & 3) * 2;
            float b0 = bias[col], b1 = bias[col + 1];
            if (ra < N_NODES) {
                float v0 = acc[mf][nf][0] + b0; v0 = v0 > 0.f ? v0 : 0.f;
                float v1 = acc[mf][nf][1] + b1; v1 = v1 > 0.f ? v1 : 0.f;
                *(uint2*)(outp + (size_t)ra * F + col) = make_uint2(pack_v(v0), pack_v(v1));
            }
            if (rb < N_NODES) {
                float v2 = acc[mf][nf][2] + b0; v2 = v2 > 0.f ? v2 : 0.f;
                float v3 = acc[mf][nf][3] + b1; v3 = v3 > 0.f ? v3 : 0.f;
                *(uint2*)(outp + (size_t)rb * F + col) = make_uint2(pack_v(v2), pack_v(v3));
            }
        }
    }
}

// ---------------- final linear ---------------------------------------------------
__global__ void k_final(const unsigned* __restrict__ h,
                        const float* __restrict__ Wf,
                        const float* __restrict__ bf,
                        float* __restrict__ out)
{
    int warp = (blockIdx.x * blockDim.x + threadIdx.x) >> 5;
    if (warp >= N_NODES) return;
    int lane = threadIdx.x & 31;
    uint4 p = ((const uint4*)(h + (size_t)warp * F))[lane];
    float4 wv = ((const float4*)Wf)[lane];
    float s = unpack_v(p.x) * wv.x + unpack_v(p.y) * wv.y +
              unpack_v(p.z) * wv.z + unpack_v(p.w) * wv.w;
#pragma unroll
    for (int o = 16; o > 0; o >>= 1) s += __shfl_down_sync(0xFFFFFFFFu, s, o);
    if (lane == 0) out[warp] = s + bf[0];
}

// ---------------- launch -----------------------------------------------------------
extern "C" void kernel_launch(void* const* d_in, const int* in_sizes, int n_in,
                              void* d_out, int out_size)
{
    const float* x    = (const float*)d_in[0];
    const int*   edge = (const int*)d_in[1];   // int32 (JAX x64 disabled)
    const float* Wl[3] = {(const float*)d_in[2], (const float*)d_in[5], (const float*)d_in[8]};
    const float* bl[3] = {(const float*)d_in[3], (const float*)d_in[6], (const float*)d_in[9]};
    const float* Wr[3] = {(const float*)d_in[4], (const float*)d_in[7], (const float*)d_in[10]};
    const float* Wf = (const float*)d_in[11];
    const float* bf = (const float*)d_in[12];
    float* out = (float*)d_out;

    cudaFuncSetAttribute(k_gemm, cudaFuncAttributeMaxDynamicSharedMemorySize, SM_TOTAL);

    void* p = nullptr;
    cudaGetSymbolAddress(&p, g_xp);
    unsigned* xp = (unsigned*)p;
    cudaGetSymbolAddress(&p, g_hp);
    unsigned* h0 = (unsigned*)p;
    unsigned* h1 = h0 + (size_t)N_NODES * F;
    cudaGetSymbolAddress(&p, g_meanp);
    unsigned* mp = (unsigned*)p;
    cudaGetSymbolAddress(&p, g_whi);
    __nv_bfloat16* whi = (__nv_bfloat16*)p;
    cudaGetSymbolAddress(&p, g_wlo);
    __nv_bfloat16* wlo = (__nv_bfloat16*)p;

    // CSR build
    k_zero_deg<<<(N_NODES + 255) / 256, 256>>>();
    k_hist<<<(N_EDGES + 255) / 256, 256>>>(edge);
    k_scan1<<<NSCAN, SCAN_BLK>>>();
    k_scan2<<<1, 64>>>();
    k_scan3<<<(N_NODES + 255) / 256, 256>>>();
    k_scatter<<<(N_EDGES + 255) / 256, 256>>>(edge);

    // pack inputs + weights
    k_pack_w<<<(3 * 128 * 256 + 255) / 256, 256>>>(Wl[0], Wr[0], Wl[1], Wr[1], Wl[2], Wr[2]);
    k_pack_x<<<(N_NODES * F / 4 + 255) / 256, 256>>>(x);

    const int AGG_BLOCKS = (N_NODES * 32 + 255) / 256;
    const int GEMM_BLOCKS = (N_NODES + 127) / 128;   // 391

    // layer 0
    k_agg<<<AGG_BLOCKS, 256>>>(xp);
    k_gemm<<<GEMM_BLOCKS, 256, SM_TOTAL>>>(mp, xp, whi, wlo, bl[0], h0);
    // layer 1
    k_agg<<<AGG_BLOCKS, 256>>>(h0);
    k_gemm<<<GEMM_BLOCKS, 256, SM_TOTAL>>>(mp, h0, whi + 128 * 256, wlo + 128 * 256, bl[1], h1);
    // layer 2
    k_agg<<<AGG_BLOCKS, 256>>>(h1);
    k_gemm<<<GEMM_BLOCKS, 256, SM_TOTAL>>>(mp, h1, whi + 2 * 128 * 256, wlo + 2 * 128 * 256, bl[2], h0);
    // final
    k_final<<<AGG_BLOCKS, 256>>>(h0, Wf, bf, out);
}